// round 7
// baseline (speedup 1.0000x reference)
#include <cuda_runtime.h>
#include <cstdint>
#include <cfloat>

// VectorQuantizer: x [N,256] fp32, emb [K,256] fp32.
// Out (fp32): quantized [N*256] | loss [1] | indices [N].
// INT8 mma.sync prefilter (rigorous runtime margin) + exact fp32-chain rescore.

#define DIM    256
#define NMAX   65536
#define KMAX   4096
#define CAP    128
#define BM     128
#define BN     128

__device__ __align__(16) float  g_S[NMAX];
__device__ __align__(16) float  g_c[KMAX];
__device__ __align__(16) float  g_sx[NMAX];
__device__ __align__(16) float  g_sxQ[NMAX];
__device__ __align__(16) float  g_se[KMAX];
__device__ __align__(16) float  g_A[KMAX];
__device__ float          g_semax, g_Amax;
__device__ float          g_margin[NMAX];
__device__ int            g_idx[NMAX];
__device__ float          g_runmin[NMAX];
__device__ unsigned int   g_cnt[NMAX];
__device__ unsigned long long g_cand[(size_t)NMAX * CAP];
__device__ __align__(16) uint32_t g_xq[(size_t)NMAX * 64];   // int8 packed
__device__ __align__(16) uint32_t g_eq[(size_t)KMAX * 64];
__device__ double         g_acc;

__device__ __forceinline__ int q8(float v, float inv) {
    int q = __float2int_rn(v * inv);
    return max(-127, min(127, q));
}

// ---------------------------------------------------------------------------
// prep: exact seq fp32 norms + int8 quantization (+aux sums for margin bound)
// ---------------------------------------------------------------------------
__global__ __launch_bounds__(256) void k_prep_x(const float* __restrict__ x, int N) {
    int n = blockIdx.x * blockDim.x + threadIdx.x;
    if (n >= N) return;
    g_cnt[n] = 0u;
    const float4* xr = (const float4*)(x + (size_t)n * DIM);
    float s = 0.0f, amax = 0.0f;
    #pragma unroll 8
    for (int i = 0; i < 64; i++) {
        float4 v = __ldg(xr + i);
        s = __fadd_rn(s, __fmul_rn(v.x, v.x));
        s = __fadd_rn(s, __fmul_rn(v.y, v.y));
        s = __fadd_rn(s, __fmul_rn(v.z, v.z));
        s = __fadd_rn(s, __fmul_rn(v.w, v.w));
        amax = fmaxf(amax, fmaxf(fmaxf(fabsf(v.x), fabsf(v.y)),
                                 fmaxf(fabsf(v.z), fabsf(v.w))));
    }
    amax = fmaxf(amax, 1e-30f);
    float sx = amax / 127.0f, inv = 127.0f / amax;
    int Q = 0;
    uint32_t* dst = g_xq + (size_t)n * 64;
    #pragma unroll 8
    for (int i = 0; i < 64; i++) {
        float4 v = __ldg(xr + i);
        int q0 = q8(v.x, inv), q1 = q8(v.y, inv), q2 = q8(v.z, inv), q3 = q8(v.w, inv);
        Q += abs(q0) + abs(q1) + abs(q2) + abs(q3);
        dst[i] = (uint32_t)(q0 & 0xff) | ((uint32_t)(q1 & 0xff) << 8)
               | ((uint32_t)(q2 & 0xff) << 16) | ((uint32_t)(q3 & 0xff) << 24);
    }
    g_S[n] = s; g_sx[n] = sx; g_sxQ[n] = sx * (float)Q;
}

__global__ __launch_bounds__(256) void k_prep_e(const float* __restrict__ emb, int K) {
    int k = blockIdx.x * blockDim.x + threadIdx.x;
    if (k >= K) return;
    const float4* er = (const float4*)(emb + (size_t)k * DIM);
    float s = 0.0f, amax = 0.0f;
    #pragma unroll 8
    for (int i = 0; i < 64; i++) {
        float4 v = __ldg(er + i);
        s = __fadd_rn(s, __fmul_rn(v.x, v.x));
        s = __fadd_rn(s, __fmul_rn(v.y, v.y));
        s = __fadd_rn(s, __fmul_rn(v.z, v.z));
        s = __fadd_rn(s, __fmul_rn(v.w, v.w));
        amax = fmaxf(amax, fmaxf(fmaxf(fabsf(v.x), fabsf(v.y)),
                                 fmaxf(fabsf(v.z), fabsf(v.w))));
    }
    amax = fmaxf(amax, 1e-30f);
    float se = amax / 127.0f, inv = 127.0f / amax;
    int P = 0;
    uint32_t* dst = g_eq + (size_t)k * 64;
    #pragma unroll 8
    for (int i = 0; i < 64; i++) {
        float4 v = __ldg(er + i);
        int q0 = q8(v.x, inv), q1 = q8(v.y, inv), q2 = q8(v.z, inv), q3 = q8(v.w, inv);
        P += abs(q0) + abs(q1) + abs(q2) + abs(q3);
        dst[i] = (uint32_t)(q0 & 0xff) | ((uint32_t)(q1 & 0xff) << 8)
               | ((uint32_t)(q2 & 0xff) << 16) | ((uint32_t)(q3 & 0xff) << 24);
    }
    g_c[k] = s; g_se[k] = se; g_A[k] = se * (float)P;
}

// single block: reduce semax/Amax over K codes; zero loss accumulator
__global__ __launch_bounds__(256) void k_red(int K) {
    __shared__ float r1[256], r2[256];
    float m1 = 0.f, m2 = 0.f;
    for (int k = threadIdx.x; k < K; k += 256) {
        m1 = fmaxf(m1, g_se[k]);
        m2 = fmaxf(m2, g_A[k]);
    }
    r1[threadIdx.x] = m1; r2[threadIdx.x] = m2;
    __syncthreads();
    for (int s = 128; s > 0; s >>= 1) {
        if (threadIdx.x < s) {
            r1[threadIdx.x] = fmaxf(r1[threadIdx.x], r1[threadIdx.x + s]);
            r2[threadIdx.x] = fmaxf(r2[threadIdx.x], r2[threadIdx.x + s]);
        }
        __syncthreads();
    }
    if (threadIdx.x == 0) { g_semax = r1[0]; g_Amax = r2[0]; g_acc = 0.0; }
}

// ---------------------------------------------------------------------------
// INT8 mma.sync prefilter GEMM (128x128 tile, 8 k32-steps, double-buffered).
// ---------------------------------------------------------------------------
__device__ __forceinline__ void cpa16(uint32_t s, const void* g) {
    asm volatile("cp.async.cg.shared.global [%0], [%1], 16;\n" :: "r"(s), "l"(g));
}
__device__ __forceinline__ void ldsm4(uint32_t* r, uint32_t a) {
    asm volatile("ldmatrix.sync.aligned.m8n8.x4.shared.b16 {%0,%1,%2,%3}, [%4];"
        : "=r"(r[0]), "=r"(r[1]), "=r"(r[2]), "=r"(r[3]) : "r"(a));
}
__device__ __forceinline__ void mma_s8(int* d, const uint32_t* a,
                                       uint32_t b0, uint32_t b1) {
    asm volatile("mma.sync.aligned.m16n8k32.row.col.s32.s8.s8.s32 "
        "{%0,%1,%2,%3}, {%4,%5,%6,%7}, {%8,%9}, {%0,%1,%2,%3};"
        : "+r"(d[0]), "+r"(d[1]), "+r"(d[2]), "+r"(d[3])
        : "r"(a[0]), "r"(a[1]), "r"(a[2]), "r"(a[3]), "r"(b0), "r"(b1));
}

// int8 tile: 128 rows x 256B; 16 units of 16B per row, XOR-swizzled
__device__ __forceinline__ uint32_t toff(int r, int j) {
    return (uint32_t)((r << 8) + ((j & 8) << 4) + (((j ^ r) & 7) << 4));
}

#define SM_XS  0
#define SM_ES  32768
#define SM_SC  (SM_ES + 2 * 32768)       // 4 x 512B c chunks
#define SM_SE  (SM_SC + 2048)            // 4 x 512B se chunks
#define SM_SS  (SM_SE + 2048)
#define SM_SX  (SM_SS + 512)
#define SM_MG  (SM_SX + 512)
#define SM_RM  (SM_MG + 512)
#define SM_TOT (SM_RM + 512)

__global__ __launch_bounds__(256, 1) void k_gemm(int N, int K) {
    extern __shared__ char smem[];
    const uint32_t sb = (uint32_t)__cvta_generic_to_shared(smem);
    float* scf = (float*)(smem + SM_SC);
    float* sse = (float*)(smem + SM_SE);
    float* sSf = (float*)(smem + SM_SS);
    float* ssx = (float*)(smem + SM_SX);
    float* smg = (float*)(smem + SM_MG);
    int*   srm = (int*)  (smem + SM_RM);

    const int tid = threadIdx.x;
    const int rb  = blockIdx.x * BM;

    if (tid < BM) {
        srm[tid] = 0x7f7fffff;
        sSf[tid] = g_S[rb + tid];
        float sx = g_sx[rb + tid];
        ssx[tid] = sx;
        float mg = 1.15f * (2.0f * g_semax * g_sxQ[rb + tid]
                          + 2.0f * sx * g_Amax
                          + 256.0f * sx * g_semax) + 2e-4f;
        smg[tid] = mg;
        g_margin[rb + tid] = mg;
    }

    // preload x tile + e chunk0(+c0,se0); then e chunk1(+c1,se1)
    const char* xq = (const char*)g_xq;
    const char* eq = (const char*)g_eq;
    for (int i = tid; i < BM * 16; i += 256) {
        int r = i >> 4, j = i & 15;
        cpa16(sb + SM_XS + toff(r, j), xq + (size_t)(rb + r) * 256 + j * 16);
        cpa16(sb + SM_ES + toff(r, j), eq + (size_t)r * 256 + j * 16);
    }
    if (tid < 32) cpa16(sb + SM_SC + tid * 16, g_c + tid * 4);
    else if (tid < 64) cpa16(sb + SM_SE + (tid - 32) * 16, g_se + (tid - 32) * 4);
    asm volatile("cp.async.commit_group;\n");
    for (int i = tid; i < BN * 16; i += 256) {
        int r = i >> 4, j = i & 15;
        cpa16(sb + SM_ES + 32768 + toff(r, j), eq + (size_t)(BN + r) * 256 + j * 16);
    }
    if (tid < 32) cpa16(sb + SM_SC + 512 + tid * 16, g_c + BN + tid * 4);
    else if (tid < 64) cpa16(sb + SM_SE + 512 + (tid - 32) * 16, g_se + BN + (tid - 32) * 4);
    asm volatile("cp.async.commit_group;\n");

    const int lane = tid & 31, wid = tid >> 5;
    const int mi = wid >> 1, ni = wid & 1;
    const int g = lane >> 2, t = lane & 3;
    const int nchunks = K / BN;

    for (int ci = 0; ci < nchunks; ci++) {
        const int buf = ci & 1;
        asm volatile("cp.async.wait_group 0;\n");
        __syncthreads();
        if (ci + 1 < nchunks) {
            const int nb = (ci + 1) & 1;
            for (int i = tid; i < BN * 16; i += 256) {
                int r = i >> 4, j = i & 15;
                cpa16(sb + SM_ES + nb * 32768 + toff(r, j),
                      eq + (size_t)((ci + 1) * BN + r) * 256 + j * 16);
            }
            if (tid < 32)
                cpa16(sb + SM_SC + ((ci + 1) & 3) * 512 + tid * 16,
                      g_c + (ci + 1) * BN + tid * 4);
            else if (tid < 64)
                cpa16(sb + SM_SE + ((ci + 1) & 3) * 512 + (tid - 32) * 16,
                      g_se + (ci + 1) * BN + (tid - 32) * 4);
            asm volatile("cp.async.commit_group;\n");
        }

        int acc[2][8][4];
        #pragma unroll
        for (int mt = 0; mt < 2; mt++)
            #pragma unroll
            for (int nf = 0; nf < 8; nf++)
                #pragma unroll
                for (int q = 0; q < 4; q++) acc[mt][nf][q] = 0;

        const uint32_t esb = sb + SM_ES + buf * 32768;
        #pragma unroll
        for (int ks = 0; ks < 8; ks++) {
            uint32_t a[2][4];
            #pragma unroll
            for (int mt = 0; mt < 2; mt++) {
                int r = mi * 32 + mt * 16 + (lane & 7) + ((lane >> 3) & 1) * 8;
                ldsm4(a[mt], sb + SM_XS + toff(r, ks * 2 + (lane >> 4)));
            }
            uint32_t b[4][4];
            #pragma unroll
            for (int nq = 0; nq < 4; nq++) {
                int r = ni * 64 + nq * 16 + (lane & 7) + (lane >> 4) * 8;
                ldsm4(b[nq], esb + toff(r, ks * 2 + ((lane >> 3) & 1)));
            }
            #pragma unroll
            for (int mt = 0; mt < 2; mt++)
                #pragma unroll
                for (int nf = 0; nf < 8; nf++)
                    mma_s8(acc[mt][nf], a[mt],
                           b[nf >> 1][(nf & 1) * 2 + 0],
                           b[nf >> 1][(nf & 1) * 2 + 1]);
        }

        const int cb = ci * BN;
        const float* scb = scf + (ci & 3) * 128;
        const float* seb = sse + (ci & 3) * 128;

        // phase A: running min
        #pragma unroll
        for (int mt = 0; mt < 2; mt++) {
            #pragma unroll
            for (int h = 0; h < 2; h++) {
                const int rl = mi * 32 + mt * 16 + g + h * 8;
                const float S = sSf[rl];
                const float m2sx = -2.0f * ssx[rl];
                float lmin = FLT_MAX;
                #pragma unroll
                for (int nf = 0; nf < 8; nf++) {
                    #pragma unroll
                    for (int q = 0; q < 2; q++) {
                        const int cl = ni * 64 + nf * 8 + t * 2 + q;
                        float w = (float)acc[mt][nf][h * 2 + q] * seb[cl];
                        float dist = __fadd_rn(__fmaf_rn(m2sx, w, S), scb[cl]);
                        lmin = fminf(lmin, dist);
                    }
                }
                lmin = fminf(lmin, __shfl_xor_sync(0xffffffffu, lmin, 1));
                lmin = fminf(lmin, __shfl_xor_sync(0xffffffffu, lmin, 2));
                if (t == 0) atomicMin(&srm[rl], __float_as_int(lmin));
            }
        }
        __syncthreads();

        // phase B: margin appends vs post-chunk running min
        #pragma unroll
        for (int mt = 0; mt < 2; mt++) {
            #pragma unroll
            for (int h = 0; h < 2; h++) {
                const int rl = mi * 32 + mt * 16 + g + h * 8;
                const float S = sSf[rl];
                const float m2sx = -2.0f * ssx[rl];
                const float rmw = __int_as_float(srm[rl]) + smg[rl];
                #pragma unroll
                for (int nf = 0; nf < 8; nf++) {
                    #pragma unroll
                    for (int q = 0; q < 2; q++) {
                        const int cl = ni * 64 + nf * 8 + t * 2 + q;
                        float w = (float)acc[mt][nf][h * 2 + q] * seb[cl];
                        float dist = __fadd_rn(__fmaf_rn(m2sx, w, S), scb[cl]);
                        if (dist <= rmw) {
                            unsigned int pos = atomicAdd(&g_cnt[rb + rl], 1u);
                            if (pos < CAP)
                                g_cand[(size_t)(rb + rl) * CAP + pos] =
                                    ((unsigned long long)__float_as_uint(dist) << 32)
                                    | (unsigned int)(cb + cl);
                        }
                    }
                }
            }
        }
        __syncthreads();
    }

    if (tid < BM) g_runmin[rb + tid] = __int_as_float(srm[tid]);
}

// ---------------------------------------------------------------------------
// Exact rescore (bit-exact chain); full-scan fallback on overflow rows.
// ---------------------------------------------------------------------------
__device__ __forceinline__ unsigned long long exact_pack(
        const float* xr, const float* emb, float Sv, unsigned int k) {
    const float* er = emb + (size_t)k * DIM;
    float m = 0.0f;
    #pragma unroll 4
    for (int i = 0; i < 64; i++) {
        float4 xv = __ldg((const float4*)xr + i);
        float4 ev = __ldg((const float4*)er + i);
        m = __fmaf_rn(xv.x, ev.x, m);
        m = __fmaf_rn(xv.y, ev.y, m);
        m = __fmaf_rn(xv.z, ev.z, m);
        m = __fmaf_rn(xv.w, ev.w, m);
    }
    float d = __fadd_rn(__fmaf_rn(-2.0f, m, Sv), g_c[k]);
    return ((unsigned long long)__float_as_uint(d) << 32) | k;
}

__global__ __launch_bounds__(256) void k_rescore(const float* __restrict__ x,
                                                 const float* __restrict__ emb,
                                                 int N, int K) {
    const int w = (blockIdx.x * blockDim.x + threadIdx.x) >> 5;
    const int lane = threadIdx.x & 31;
    if (w >= N) return;
    const unsigned int cnt = g_cnt[w];
    const float Sv  = g_S[w];
    const float* xr = x + (size_t)w * DIM;
    unsigned long long best = 0xffffffffffffffffULL;
    if (cnt <= CAP) {
        const float thr = g_runmin[w] + g_margin[w];
        for (unsigned int e = lane; e < cnt; e += 32) {
            unsigned long long ent = g_cand[(size_t)w * CAP + e];
            float dt = __uint_as_float((unsigned int)(ent >> 32));
            if (dt > thr) continue;
            unsigned long long v =
                exact_pack(xr, emb, Sv, (unsigned int)(ent & 0xffffffffu));
            if (v < best) best = v;
        }
    } else {
        for (int k = lane; k < K; k += 32) {
            unsigned long long v = exact_pack(xr, emb, Sv, (unsigned int)k);
            if (v < best) best = v;
        }
    }
    #pragma unroll
    for (int o = 16; o; o >>= 1) {
        unsigned long long v = __shfl_xor_sync(0xffffffffu, best, o);
        if (v < best) best = v;
    }
    if (lane == 0) g_idx[w] = (int)(best & 0xffffffffu);
}

// ---------------------------------------------------------------------------
// Epilogue: grid-stride, one fp64 atomic per block.
// ---------------------------------------------------------------------------
__global__ __launch_bounds__(256) void k_epi(const float* __restrict__ x,
                                             const float* __restrict__ emb,
                                             float* __restrict__ out,
                                             float* __restrict__ outIdx, int N) {
    __shared__ double red[256];
    const int nvec = N * (DIM / 4);
    const int stride = gridDim.x * blockDim.x;
    double ls = 0.0;
    for (int tno = blockIdx.x * blockDim.x + threadIdx.x; tno < nvec; tno += stride) {
        const int n   = tno >> 6;
        const int idx = g_idx[n];
        const float4 xv = reinterpret_cast<const float4*>(x)[tno];
        const float4 ev = reinterpret_cast<const float4*>(emb)
                              [(size_t)idx * (DIM / 4) + (tno & 63)];
        float d0 = __fsub_rn(ev.x, xv.x), d1 = __fsub_rn(ev.y, xv.y);
        float d2 = __fsub_rn(ev.z, xv.z), d3 = __fsub_rn(ev.w, xv.w);
        float4 o;
        o.x = __fadd_rn(xv.x, d0); o.y = __fadd_rn(xv.y, d1);
        o.z = __fadd_rn(xv.z, d2); o.w = __fadd_rn(xv.w, d3);
        reinterpret_cast<float4*>(out)[tno] = o;
        ls += (double)__fmul_rn(d0, d0) + (double)__fmul_rn(d1, d1)
            + (double)__fmul_rn(d2, d2) + (double)__fmul_rn(d3, d3);
        if (outIdx != nullptr && (tno & 63) == 0) outIdx[n] = (float)idx;
    }
    red[threadIdx.x] = ls;
    __syncthreads();
    #pragma unroll
    for (int s = 128; s > 0; s >>= 1) {
        if (threadIdx.x < s) red[threadIdx.x] += red[threadIdx.x + s];
        __syncthreads();
    }
    if (threadIdx.x == 0) atomicAdd(&g_acc, red[0]);
}

__global__ void k_fin(float* __restrict__ out, int N) {
    double m = g_acc / ((double)N * (double)DIM);
    float L = (float)m;
    out[(size_t)N * DIM] = __fadd_rn(L, __fmul_rn(0.25f, L));
}

// ---------------------------------------------------------------------------
extern "C" void kernel_launch(void* const* d_in, const int* in_sizes, int n_in,
                              void* d_out, int out_size) {
    const float* x   = (const float*)d_in[0];
    const float* emb = (const float*)d_in[1];
    const int N = in_sizes[0] / DIM;
    const int K = in_sizes[1] / DIM;
    float* out = (float*)d_out;

    const long long Nq = (long long)N * DIM;
    const bool has_loss = (long long)out_size > Nq;
    const bool has_idx  = (long long)out_size >= Nq + 1 + N;
    float* outIdx = has_idx ? out + Nq + 1 : nullptr;

    cudaFuncSetAttribute(k_gemm, cudaFuncAttributeMaxDynamicSharedMemorySize,
                         SM_TOT);

    k_prep_e<<<(K + 255) / 256, 256>>>(emb, K);
    k_red<<<1, 256>>>(K);
    k_prep_x<<<(N + 255) / 256, 256>>>(x, N);
    k_gemm<<<N / BM, 256, SM_TOT>>>(N, K);
    k_rescore<<<(N * 32 + 255) / 256, 256>>>(x, emb, N, K);
    k_epi<<<1184, 256>>>(x, emb, out, outIdx, N);
    if (has_loss) k_fin<<<1, 1>>>(out, N);
}

// round 8
// speedup vs baseline: 2.6543x; 2.6543x over previous
#include <cuda_runtime.h>
#include <cuda_bf16.h>
#include <cstdint>
#include <cfloat>

// VectorQuantizer: x [N,256] fp32, emb [K,256] fp32.
// Out (fp32): quantized [N*256] | loss [1] | indices [N].
// bf16 legacy-mma prefilter (margin 2e-3, proven exact in R4) + fused
// per-block exact rescore + quantize/loss epilogue.

#define DIM   256
#define NMAX  65536
#define KMAX  4096
#define CAP   128
#define MG    2e-3f
#define BM    64
#define BN    64
#define NCH   (KMAX / BN)

__device__ __align__(16) float  g_S[NMAX];
__device__ __align__(16) float  g_c[KMAX];
__device__ unsigned int   g_cnt[NMAX];
__device__ unsigned long long g_cand[(size_t)NMAX * CAP];
__device__ __align__(16) __nv_bfloat16 g_xb[(size_t)NMAX * DIM];
__device__ __align__(16) __nv_bfloat16 g_eb[(size_t)KMAX * DIM];
__device__ double         g_acc;

// ---------------------------------------------------------------------------
// Fused prep: bf16 convert + exact seq fp32 norms + resets.
// ---------------------------------------------------------------------------
__global__ __launch_bounds__(256) void k_prep_x(const float* __restrict__ x, int N) {
    int n = blockIdx.x * blockDim.x + threadIdx.x;
    if (n >= N) return;
    g_cnt[n] = 0u;
    const float4* xr = (const float4*)(x + (size_t)n * DIM);
    __nv_bfloat162* dst = (__nv_bfloat162*)(g_xb + (size_t)n * DIM);
    float s = 0.0f;
    #pragma unroll 8
    for (int i = 0; i < 64; i++) {
        float4 v = __ldg(xr + i);
        s = __fadd_rn(s, __fmul_rn(v.x, v.x));
        s = __fadd_rn(s, __fmul_rn(v.y, v.y));
        s = __fadd_rn(s, __fmul_rn(v.z, v.z));
        s = __fadd_rn(s, __fmul_rn(v.w, v.w));
        dst[2 * i + 0] = __floats2bfloat162_rn(v.x, v.y);
        dst[2 * i + 1] = __floats2bfloat162_rn(v.z, v.w);
    }
    g_S[n] = s;
}

__global__ __launch_bounds__(256) void k_prep_e(const float* __restrict__ emb, int K) {
    int k = blockIdx.x * blockDim.x + threadIdx.x;
    if (k == 0) g_acc = 0.0;
    if (k >= K) return;
    const float4* er = (const float4*)(emb + (size_t)k * DIM);
    __nv_bfloat162* dst = (__nv_bfloat162*)(g_eb + (size_t)k * DIM);
    float s = 0.0f;
    #pragma unroll 8
    for (int i = 0; i < 64; i++) {
        float4 v = __ldg(er + i);
        s = __fadd_rn(s, __fmul_rn(v.x, v.x));
        s = __fadd_rn(s, __fmul_rn(v.y, v.y));
        s = __fadd_rn(s, __fmul_rn(v.z, v.z));
        s = __fadd_rn(s, __fmul_rn(v.w, v.w));
        dst[2 * i + 0] = __floats2bfloat162_rn(v.x, v.y);
        dst[2 * i + 1] = __floats2bfloat162_rn(v.z, v.w);
    }
    g_c[k] = s;
}

// ---------------------------------------------------------------------------
__device__ __forceinline__ void cpa16(uint32_t s, const void* g) {
    asm volatile("cp.async.cg.shared.global [%0], [%1], 16;\n" :: "r"(s), "l"(g));
}
__device__ __forceinline__ void ldsm4(uint32_t* r, uint32_t a) {
    asm volatile("ldmatrix.sync.aligned.m8n8.x4.shared.b16 {%0,%1,%2,%3}, [%4];"
        : "=r"(r[0]), "=r"(r[1]), "=r"(r[2]), "=r"(r[3]) : "r"(a));
}
__device__ __forceinline__ void mma16816(float* d, const uint32_t* a,
                                         uint32_t b0, uint32_t b1) {
    asm volatile("mma.sync.aligned.m16n8k16.row.col.f32.bf16.bf16.f32 "
        "{%0,%1,%2,%3}, {%4,%5,%6,%7}, {%8,%9}, {%0,%1,%2,%3};"
        : "+f"(d[0]), "+f"(d[1]), "+f"(d[2]), "+f"(d[3])
        : "r"(a[0]), "r"(a[1]), "r"(a[2]), "r"(a[3]), "r"(b0), "r"(b1));
}

// 64-row bf16 tile: row r = 512B, 32 units of 16B, low-3-bit XOR swizzle
__device__ __forceinline__ uint32_t xoff(int r, int j) {
    return (uint32_t)((r << 9) + (((j & 24) | ((j ^ r) & 7)) << 4));
}

// smem map (bytes)
#define SM_XS  0                       // 64*512 = 32768
#define SM_ES  32768                   // 2 * 32768
#define SM_SC  (SM_ES + 2 * 32768)     // 2 * 256B c chunks
#define SM_SS  (SM_SC + 512)           // 64 * 4
#define SM_RM  (SM_SS + 256)           // 64 * 4
#define SM_SI  (SM_RM + 256)           // 64 * 4 (final indices)
#define SM_DR  (SM_SI + 256)           // 8 doubles
#define SM_TOT (SM_DR + 64)

__device__ __forceinline__ unsigned long long exact_pack(
        const float* xr, const float* emb, float Sv, unsigned int k) {
    const float* er = emb + (size_t)k * DIM;
    float m = 0.0f;
    #pragma unroll 4
    for (int i = 0; i < 64; i++) {
        float4 xv = __ldg((const float4*)xr + i);
        float4 ev = __ldg((const float4*)er + i);
        m = __fmaf_rn(xv.x, ev.x, m);
        m = __fmaf_rn(xv.y, ev.y, m);
        m = __fmaf_rn(xv.z, ev.z, m);
        m = __fmaf_rn(xv.w, ev.w, m);
    }
    float d = __fadd_rn(__fmaf_rn(-2.0f, m, Sv), g_c[k]);
    return ((unsigned long long)__float_as_uint(d) << 32) | k;
}

__global__ __launch_bounds__(256, 2) void k_gemm(const float* __restrict__ x,
                                                 const float* __restrict__ emb,
                                                 float* __restrict__ out,
                                                 float* __restrict__ outIdx,
                                                 int N, int K) {
    extern __shared__ char smem[];
    const uint32_t sb = (uint32_t)__cvta_generic_to_shared(smem);
    float*  sS   = (float*)(smem + SM_SS);
    int*    srm  = (int*)  (smem + SM_RM);
    int*    sidx = (int*)  (smem + SM_SI);
    double* sred = (double*)(smem + SM_DR);

    const int tid  = threadIdx.x;
    const int lane = tid & 31, wid = tid >> 5;
    const int rb   = blockIdx.x * BM;

    if (tid < BM) { srm[tid] = 0x7f7fffff; sS[tid] = g_S[rb + tid]; }

    // preload x tile + e chunk 0 + c chunk 0 (one group)
    for (int i = tid; i < BM * 32; i += 256) {
        int r = i >> 5, j = i & 31;
        cpa16(sb + SM_XS + xoff(r, j), g_xb + (size_t)(rb + r) * DIM + j * 8);
        cpa16(sb + SM_ES + xoff(r, j), g_eb + (size_t)r * DIM + j * 8);
    }
    if (tid < 16) cpa16(sb + SM_SC + tid * 16, g_c + tid * 4);
    asm volatile("cp.async.commit_group;\n");

    const int mi = wid >> 2;       // 0..1 : 32-row group
    const int ni = wid & 3;        // 0..3 : 16-col group
    const int g  = lane >> 2, t = lane & 3;

    for (int ci = 0; ci < NCH; ci++) {
        const int buf = ci & 1;
        asm volatile("cp.async.wait_group 0;\n");
        __syncthreads();

        // prefetch chunk ci+1 (overlaps this chunk's compute)
        if (ci + 1 < NCH) {
            const int nb = (ci + 1) & 1;
            for (int i = tid; i < BN * 32; i += 256) {
                int r = i >> 5, j = i & 31;
                cpa16(sb + SM_ES + nb * 32768 + xoff(r, j),
                      g_eb + (size_t)((ci + 1) * BN + r) * DIM + j * 8);
            }
            if (tid < 16) cpa16(sb + SM_SC + nb * 256 + tid * 16,
                                g_c + (ci + 1) * BN + tid * 4);
            asm volatile("cp.async.commit_group;\n");
        }

        float acc[2][2][4];
        #pragma unroll
        for (int mt = 0; mt < 2; mt++)
            #pragma unroll
            for (int nf = 0; nf < 2; nf++)
                #pragma unroll
                for (int q = 0; q < 4; q++) acc[mt][nf][q] = 0.0f;

        const uint32_t esb = sb + SM_ES + buf * 32768;
        #pragma unroll
        for (int ks = 0; ks < 16; ks++) {
            uint32_t a[2][4], b[4];
            #pragma unroll
            for (int mt = 0; mt < 2; mt++) {
                int r = mi * 32 + mt * 16 + (lane & 7) + ((lane >> 3) & 1) * 8;
                ldsm4(a[mt], sb + SM_XS + xoff(r, ks * 2 + (lane >> 4)));
            }
            {
                int r = ni * 16 + (lane & 7) + (lane >> 4) * 8;
                ldsm4(b, esb + xoff(r, ks * 2 + ((lane >> 3) & 1)));
            }
            #pragma unroll
            for (int mt = 0; mt < 2; mt++) {
                mma16816(acc[mt][0], a[mt], b[0], b[1]);
                mma16816(acc[mt][1], a[mt], b[2], b[3]);
            }
        }

        // distances in place: acc <- fadd(fma(-2,acc,S), c)
        const float* scb = (const float*)(smem + SM_SC + buf * 256);
        #pragma unroll
        for (int mt = 0; mt < 2; mt++)
            #pragma unroll
            for (int nf = 0; nf < 2; nf++)
                #pragma unroll
                for (int h = 0; h < 2; h++)
                    #pragma unroll
                    for (int q = 0; q < 2; q++) {
                        const int rl = mi * 32 + mt * 16 + g + h * 8;
                        const int cl = ni * 16 + nf * 8 + 2 * t + q;
                        acc[mt][nf][h * 2 + q] = __fadd_rn(
                            __fmaf_rn(-2.0f, acc[mt][nf][h * 2 + q], sS[rl]),
                            scb[cl]);
                    }

        const int cbase = ci * BN + ni * 16;
        if (ci == 0) {
            // two-phase for the first chunk (runmin not yet seeded)
            #pragma unroll
            for (int mt = 0; mt < 2; mt++)
                #pragma unroll
                for (int h = 0; h < 2; h++) {
                    const int rl = mi * 32 + mt * 16 + g + h * 8;
                    float lmin = fminf(fminf(acc[mt][0][h * 2], acc[mt][0][h * 2 + 1]),
                                       fminf(acc[mt][1][h * 2], acc[mt][1][h * 2 + 1]));
                    lmin = fminf(lmin, __shfl_xor_sync(0xffffffffu, lmin, 1));
                    lmin = fminf(lmin, __shfl_xor_sync(0xffffffffu, lmin, 2));
                    if (t == 0) atomicMin(&srm[rl], __float_as_int(lmin));
                }
            __syncthreads();
        }
        // appends vs (possibly stale) running min — superset-safe
        #pragma unroll
        for (int mt = 0; mt < 2; mt++)
            #pragma unroll
            for (int h = 0; h < 2; h++) {
                const int rl  = mi * 32 + mt * 16 + g + h * 8;
                const float rmw = __int_as_float(srm[rl]) + MG;
                float lmin = FLT_MAX;
                #pragma unroll
                for (int nf = 0; nf < 2; nf++)
                    #pragma unroll
                    for (int q = 0; q < 2; q++) {
                        float dist = acc[mt][nf][h * 2 + q];
                        lmin = fminf(lmin, dist);
                        if (dist <= rmw) {
                            unsigned int pos = atomicAdd(&g_cnt[rb + rl], 1u);
                            if (pos < CAP)
                                g_cand[(size_t)(rb + rl) * CAP + pos] =
                                    ((unsigned long long)__float_as_uint(dist) << 32)
                                    | (unsigned int)(cbase + nf * 8 + 2 * t + q);
                        }
                    }
                if (ci > 0) {   // chunk 0 already folded its min in phase A
                    lmin = fminf(lmin, __shfl_xor_sync(0xffffffffu, lmin, 1));
                    lmin = fminf(lmin, __shfl_xor_sync(0xffffffffu, lmin, 2));
                    if (t == 0) atomicMin(&srm[rl], __float_as_int(lmin));
                }
            }
    }
    __syncthreads();

    // ---- fused tail 1: exact rescore (one warp per row, 8 rows/warp) ----
    for (int rr = wid; rr < BM; rr += 8) {
        const int n = rb + rr;
        const unsigned int cnt = g_cnt[n];
        const float Sv  = sS[rr];
        const float thr = __int_as_float(srm[rr]) + MG;
        const float* xr = x + (size_t)n * DIM;
        unsigned long long best = 0xffffffffffffffffULL;
        if (cnt <= CAP) {
            for (unsigned int e = lane; e < cnt; e += 32) {
                unsigned long long ent = g_cand[(size_t)n * CAP + e];
                float dt = __uint_as_float((unsigned int)(ent >> 32));
                if (dt > thr) continue;
                unsigned long long v =
                    exact_pack(xr, emb, Sv, (unsigned int)(ent & 0xffffffffu));
                if (v < best) best = v;
            }
        } else {  // overflow fallback: exact full scan
            for (int k = lane; k < K; k += 32) {
                unsigned long long v = exact_pack(xr, emb, Sv, (unsigned int)k);
                if (v < best) best = v;
            }
        }
        #pragma unroll
        for (int o = 16; o; o >>= 1) {
            unsigned long long v = __shfl_xor_sync(0xffffffffu, best, o);
            if (v < best) best = v;
        }
        if (lane == 0) sidx[rr] = (int)(best & 0xffffffffu);
    }
    __syncthreads();

    // ---- fused tail 2: quantized output + loss partial + indices ----
    double ls = 0.0;
    for (int rr = wid; rr < BM; rr += 8) {
        const int n = rb + rr;
        const int idx = sidx[rr];
        if (lane == 0 && outIdx != nullptr) outIdx[n] = (float)idx;
        const float4* xv4 = (const float4*)(x + (size_t)n * DIM);
        const float4* ev4 = (const float4*)(emb + (size_t)idx * DIM);
        float4* ov4 = (float4*)(out + (size_t)n * DIM);
        for (int i = lane; i < 64; i += 32) {
            float4 xv = __ldg(xv4 + i);
            float4 ev = __ldg(ev4 + i);
            float d0 = __fsub_rn(ev.x, xv.x), d1 = __fsub_rn(ev.y, xv.y);
            float d2 = __fsub_rn(ev.z, xv.z), d3 = __fsub_rn(ev.w, xv.w);
            float4 o;
            o.x = __fadd_rn(xv.x, d0); o.y = __fadd_rn(xv.y, d1);
            o.z = __fadd_rn(xv.z, d2); o.w = __fadd_rn(xv.w, d3);
            ov4[i] = o;
            ls += (double)__fmul_rn(d0, d0) + (double)__fmul_rn(d1, d1)
                + (double)__fmul_rn(d2, d2) + (double)__fmul_rn(d3, d3);
        }
    }
    #pragma unroll
    for (int o = 16; o; o >>= 1) ls += __shfl_xor_sync(0xffffffffu, ls, o);
    if (lane == 0) sred[wid] = ls;
    __syncthreads();
    if (tid == 0) {
        double s = 0.0;
        #pragma unroll
        for (int w = 0; w < 8; w++) s += sred[w];
        atomicAdd(&g_acc, s);
    }
}

__global__ void k_fin(float* __restrict__ out, int N) {
    double m = g_acc / ((double)N * (double)DIM);
    float L = (float)m;
    out[(size_t)N * DIM] = __fadd_rn(L, __fmul_rn(0.25f, L));
}

// ---------------------------------------------------------------------------
extern "C" void kernel_launch(void* const* d_in, const int* in_sizes, int n_in,
                              void* d_out, int out_size) {
    const float* x   = (const float*)d_in[0];
    const float* emb = (const float*)d_in[1];
    const int N = in_sizes[0] / DIM;
    const int K = in_sizes[1] / DIM;
    float* out = (float*)d_out;

    const long long Nq = (long long)N * DIM;
    const bool has_loss = (long long)out_size > Nq;
    const bool has_idx  = (long long)out_size >= Nq + 1 + N;
    float* outIdx = has_idx ? out + Nq + 1 : nullptr;

    cudaFuncSetAttribute(k_gemm, cudaFuncAttributeMaxDynamicSharedMemorySize,
                         SM_TOT);

    k_prep_e<<<(K + 255) / 256, 256>>>(emb, K);
    k_prep_x<<<(N + 255) / 256, 256>>>(x, N);
    k_gemm<<<N / BM, 256, SM_TOT>>>(x, emb, out, outIdx, N, K);
    if (has_loss) k_fin<<<1, 1>>>(out, N);
}